// round 8
// baseline (speedup 1.0000x reference)
#include <cuda_runtime.h>
#include <cstdint>
#include <math.h>

#define B_   8192
#define N_   4096
#define H_   256
#define NM_  2048
#define NLAY_ 8

typedef unsigned long long u64;

// ---------------------------------------------------------------------------
// Scratch (static device globals — no allocation)
// ---------------------------------------------------------------------------
__device__ __align__(256) float g_A [(size_t)B_ * NM_];   // 64 MB  masked half (dense fp32)
__device__ __align__(256) float g_h1[(size_t)B_ * H_];    //  8 MB
__device__ __align__(256) float g_h2[(size_t)B_ * H_];    //  8 MB

// ---------------------------------------------------------------------------
// Helpers
// ---------------------------------------------------------------------------
__device__ __forceinline__ uint32_t smem_u32(const void* p) {
    uint32_t a;
    asm("{ .reg .u64 t; cvta.to.shared.u64 t, %1; cvt.u32.u64 %0, t; }" : "=r"(a) : "l"(p));
    return a;
}

#define CPA16(sm, gp) \
    asm volatile("cp.async.cg.shared.global [%0], [%1], 16;" :: "r"(sm), "l"(gp) : "memory")
#define CP_COMMIT() asm volatile("cp.async.commit_group;" ::: "memory")
#define CP_WAIT0()  asm volatile("cp.async.wait_group 0;" ::: "memory")

// packed fp32x2 FMA: d = a*b + d (both halves)
__device__ __forceinline__ void fma2(u64& d, u64 a, u64 b) {
    asm("fma.rn.f32x2 %0, %1, %2, %0;" : "+l"(d) : "l"(a), "l"(b));
}
__device__ __forceinline__ float2 u2f(u64 v) {
    float2 f;
    f.x = __uint_as_float((unsigned)v);
    f.y = __uint_as_float((unsigned)(v >> 32));
    return f;
}
__device__ __forceinline__ u64 dupf(float v) {
    u64 b = (u64)__float_as_uint(v);
    return b | (b << 32);
}

// checkerboard index math
__device__ __forceinline__ int gather_im(int c, int p) {
    int g = c >> 5, m = c & 31;
    return g * 64 + 2 * m + ((p + g) & 1);
}
__device__ __forceinline__ int gather_iu(int c, int p) {
    int g = c >> 5, m = c & 31;
    return g * 64 + 2 * m + ((p + g + 1) & 1);
}

// ---------------------------------------------------------------------------
// Init: x = z, logdet = 0, g_A = z[:, im(parity=0)]
// ---------------------------------------------------------------------------
__global__ void init_kernel(const float* __restrict__ z, float* __restrict__ x,
                            float* __restrict__ logdet) {
    const int r = blockIdx.x;
    const int tid = threadIdx.x;
    const float4* zr = (const float4*)(z + (size_t)r * N_);
    float4* xr = (float4*)(x + (size_t)r * N_);
#pragma unroll
    for (int i = tid; i < N_ / 4; i += 256) xr[i] = zr[i];
    const float* zrow = z + (size_t)r * N_;
#pragma unroll
    for (int c = tid; c < NM_; c += 256) g_A[(size_t)r * NM_ + c] = zrow[gather_im(c, 0)];
    if (tid == 0) logdet[r] = 0.0f;
}

// ---------------------------------------------------------------------------
// f32x2 SGEMM:  D[32 x 128] = A[32 x K_TOT] @ W-slice (+bias+act / fused update)
//   CTA: 128 threads, target 6+ CTAs/SM. Thread tile 4 rows x (4 + 4) cols.
//   Double-buffered A (dup-pair u64) and B smem; ONE __syncthreads per stage.
//   ASRC: 0=g_A 1=g_h1 2=g_h2.  W native [K][ldw].
//   MODE 0: leaky -> CDST (1=g_h1, 2=g_h2), cols bx*128..
//   MODE 1: cols {bx*64 (s)} U {2048+bx*64 (t)}; fused coupling update.
// ---------------------------------------------------------------------------
template <int K_TOT, int ASRC, int MODE, int CDST>
__global__ void __launch_bounds__(128, 6)
gemm_f32x2(const float* __restrict__ W, int ldw,
           const float* __restrict__ bias, float* __restrict__ x,
           float* __restrict__ logdet, int parity) {
    __shared__ u64   As2[2][16][32];      //  8 KB total (k-major, dup pairs)
    __shared__ float Bs[2][16][128];      // 16 KB total

    const int tid  = threadIdx.x;
    const int row0 = blockIdx.y * 32;
    const int bx   = blockIdx.x;
    const int tRow = (tid >> 4) * 4;      // 0..28
    const int nOff = (tid & 15) * 4;      // 0..60
    constexpr int NS = K_TOT / 16;

    const float* Aptr = (ASRC == 0) ? g_A : (ASRC == 1) ? g_h1 : g_h2;
    Aptr += (size_t)row0 * K_TOT;

    const uint32_t bsBase = smem_u32(&Bs[0][0][0]);

    auto loadB = [&](int kt, int buf) {
#pragma unroll
        for (int i = 0; i < 4; i++) {
            const int ch = tid + i * 128;          // 0..511
            const int k  = ch >> 5;                // 0..15
            if (MODE == 1) {
                const int seg = (ch >> 4) & 1;
                const int c   = ch & 15;
                const int col = (seg ? 2048 + bx * 64 : bx * 64) + c * 4;
                const uint32_t so = bsBase + buf * 8192 + (k * 128 + seg * 64 + c * 4) * 4;
                CPA16(so, W + (size_t)(kt + k) * ldw + col);
            } else {
                const int c = ch & 31;
                const int col = bx * 128 + c * 4;
                const uint32_t so = bsBase + buf * 8192 + (k * 128 + c * 4) * 4;
                CPA16(so, W + (size_t)(kt + k) * ldw + col);
            }
        }
        CP_COMMIT();
    };

    // A loader: 32 rows x 4 float4-chunks = 128 chunks, 1 per thread
    const int aRow = tid >> 2;            // 0..31
    const int aKq  = tid & 3;             // 0..3
    auto loadA = [&](int kt, float4& ar) {
        ar = *(const float4*)(Aptr + (size_t)aRow * K_TOT + kt + aKq * 4);
    };
    auto storeA = [&](const float4& ar, int buf) {
        As2[buf][aKq * 4 + 0][aRow] = dupf(ar.x);
        As2[buf][aKq * 4 + 1][aRow] = dupf(ar.y);
        As2[buf][aKq * 4 + 2][aRow] = dupf(ar.z);
        As2[buf][aKq * 4 + 3][aRow] = dupf(ar.w);
    };

    u64 acc[4][4];
#pragma unroll
    for (int i = 0; i < 4; i++)
#pragma unroll
        for (int j = 0; j < 4; j++) acc[i][j] = 0ULL;

    // ---- prologue ----
    {
        float4 ar;
        loadB(0, 0);
        loadA(0, ar);
        storeA(ar, 0);
        CP_WAIT0();
        __syncthreads();
    }

    // ---- main loop: one barrier per stage ----
    for (int c = 0; c < NS; c++) {
        float4 ar;
        const int nb = (c + 1) & 1;
        if (c + 1 < NS) {
            loadA((c + 1) * 16, ar);
            loadB((c + 1) * 16, nb);
        }
        {
            const int buf = c & 1;
#pragma unroll
            for (int k = 0; k < 16; k++) {
                u64 a[4];
                {
                    ulonglong2 av0 = *(const ulonglong2*)&As2[buf][k][tRow];
                    ulonglong2 av1 = *(const ulonglong2*)&As2[buf][k][tRow + 2];
                    a[0] = av0.x; a[1] = av0.y; a[2] = av1.x; a[3] = av1.y;
                }
                const ulonglong2 b0 = *(const ulonglong2*)&Bs[buf][k][nOff];
                const ulonglong2 b1 = *(const ulonglong2*)&Bs[buf][k][nOff + 64];
#pragma unroll
                for (int i = 0; i < 4; i++) {
                    fma2(acc[i][0], a[i], b0.x);
                    fma2(acc[i][1], a[i], b0.y);
                    fma2(acc[i][2], a[i], b1.x);
                    fma2(acc[i][3], a[i], b1.y);
                }
            }
        }
        if (c + 1 < NS) {
            storeA(ar, nb);
            CP_WAIT0();
        }
        __syncthreads();
    }

    // ---- epilogue ----
    if (MODE == 0) {
        float* Out = (CDST == 1) ? g_h1 : g_h2;
        const int c0 = bx * 128 + nOff;
        const int c1 = c0 + 64;
        const float bl0 = bias[c0], bl1 = bias[c0 + 1], bl2 = bias[c0 + 2], bl3 = bias[c0 + 3];
        const float bh0 = bias[c1], bh1 = bias[c1 + 1], bh2 = bias[c1 + 2], bh3 = bias[c1 + 3];
#pragma unroll
        for (int i = 0; i < 4; i++) {
            const int r = row0 + tRow + i;
            float2 p0 = u2f(acc[i][0]), p1 = u2f(acc[i][1]);
            float2 p2 = u2f(acc[i][2]), p3 = u2f(acc[i][3]);
            float4 v0, v1;
            v0.x = p0.x + bl0; v0.y = p0.y + bl1; v0.z = p1.x + bl2; v0.w = p1.y + bl3;
            v1.x = p2.x + bh0; v1.y = p2.y + bh1; v1.z = p3.x + bh2; v1.w = p3.y + bh3;
            v0.x = v0.x > 0.f ? v0.x : 0.2f * v0.x;
            v0.y = v0.y > 0.f ? v0.y : 0.2f * v0.y;
            v0.z = v0.z > 0.f ? v0.z : 0.2f * v0.z;
            v0.w = v0.w > 0.f ? v0.w : 0.2f * v0.w;
            v1.x = v1.x > 0.f ? v1.x : 0.2f * v1.x;
            v1.y = v1.y > 0.f ? v1.y : 0.2f * v1.y;
            v1.z = v1.z > 0.f ? v1.z : 0.2f * v1.z;
            v1.w = v1.w > 0.f ? v1.w : 0.2f * v1.w;
            *(float4*)(Out + (size_t)r * H_ + c0) = v0;
            *(float4*)(Out + (size_t)r * H_ + c1) = v1;
        }
    } else {
        const int cs0 = bx * 64 + nOff;
        const float bs0 = bias[cs0], bs1 = bias[cs0 + 1], bs2 = bias[cs0 + 2], bs3 = bias[cs0 + 3];
        const float bt0 = bias[2048 + cs0], bt1 = bias[2048 + cs0 + 1];
        const float bt2 = bias[2048 + cs0 + 2], bt3 = bias[2048 + cs0 + 3];
        const int j0 = gather_iu(cs0, parity);
        const int j1 = gather_iu(cs0 + 1, parity);
        const int j2 = gather_iu(cs0 + 2, parity);
        const int j3 = gather_iu(cs0 + 3, parity);
#pragma unroll
        for (int i = 0; i < 4; i++) {
            const int r = row0 + tRow + i;
            float* xrow = x + (size_t)r * N_;
            float* arow = g_A + (size_t)r * NM_;
            float2 s01 = u2f(acc[i][0]), s23 = u2f(acc[i][1]);
            float2 t01 = u2f(acc[i][2]), t23 = u2f(acc[i][3]);
            float sp[4] = { s01.x + bs0, s01.y + bs1, s23.x + bs2, s23.y + bs3 };
            float tp[4] = { t01.x + bt0, t01.y + bt1, t23.x + bt2, t23.y + bt3 };
            const int jc[4] = { j0, j1, j2, j3 };
            float ssum = 0.0f;
#pragma unroll
            for (int q = 0; q < 4; q++) {
                const float e2u = __expf(2.0f * sp[q]);        // tanh via exp
                const float s   = 2.0f - 4.0f / (e2u + 1.0f);  // 2*tanh(sp)
                const float nv  = xrow[jc[q]] * __expf(s) + tp[q];
                xrow[jc[q]] = nv;
                arow[cs0 + q] = nv;
                ssum += s;
            }
            ssum += __shfl_xor_sync(0xffffffffu, ssum, 1);
            ssum += __shfl_xor_sync(0xffffffffu, ssum, 2);
            ssum += __shfl_xor_sync(0xffffffffu, ssum, 4);
            ssum += __shfl_xor_sync(0xffffffffu, ssum, 8);
            if ((tid & 15) == 0) atomicAdd(&logdet[r], ssum);
        }
    }
}

// ---------------------------------------------------------------------------
// Launch
// ---------------------------------------------------------------------------
extern "C" void kernel_launch(void* const* d_in, const int* in_sizes, int n_in,
                              void* d_out, int out_size) {
    const float* z  = (const float*)d_in[0];
    const float* W1 = (const float*)d_in[1];
    const float* b1 = (const float*)d_in[2];
    const float* W2 = (const float*)d_in[3];
    const float* b2 = (const float*)d_in[4];
    const float* W3 = (const float*)d_in[5];
    const float* b3 = (const float*)d_in[6];

    float* x      = (float*)d_out;
    float* logdet = x + (size_t)B_ * N_;

    init_kernel<<<B_, 256>>>(z, x, logdet);

    for (int l = 0; l < NLAY_; l++) {
        const int p = l & 1;
        const float* w1 = W1 + (size_t)l * NM_ * H_;
        const float* w2 = W2 + (size_t)l * H_ * H_;
        const float* w3 = W3 + (size_t)l * H_ * N_;

        // h1 = leaky( A @ W1 + b1 )      (8192x2048)(2048x256): 512 CTAs
        gemm_f32x2<NM_, 0, 0, 1><<<dim3(2, B_ / 32), 128>>>(w1, H_, b1 + (size_t)l * H_, x, logdet, p);
        // h2 = leaky( h1 @ W2 + b2 )     (8192x256)(256x256): 512 CTAs
        gemm_f32x2<H_, 1, 0, 2><<<dim3(2, B_ / 32), 128>>>(w2, H_, b2 + (size_t)l * H_, x, logdet, p);
        // fused: st = h2 @ W3 + b3 ; coupling update + next-layer A: 8192 CTAs
        gemm_f32x2<H_, 2, 1, 0><<<dim3(32, B_ / 32), 128>>>(w3, N_, b3 + (size_t)l * N_, x, logdet, p);
    }
}

// round 9
// speedup vs baseline: 1.1948x; 1.1948x over previous
#include <cuda_runtime.h>
#include <cstdint>
#include <math.h>

#define B_   8192
#define N_   4096
#define H_   256
#define NM_  2048
#define NLAY_ 8

typedef unsigned long long u64;

// ---------------------------------------------------------------------------
// Scratch (static device globals — no allocation)
// Dense checkerboard halves: D0 = cells with (i+j) even (c-order = im(.,0)),
// D1 = cells with (i+j) odd (c-order = iu(.,0)). Layers alternate roles.
// ---------------------------------------------------------------------------
__device__ __align__(256) float g_D0[(size_t)B_ * NM_];     // 64 MB
__device__ __align__(256) float g_D1[(size_t)B_ * NM_];     // 64 MB
__device__ __align__(256) float g_p [2 * (size_t)B_ * H_];  // 16 MB GEMM1 K-split partials
__device__ __align__(256) float g_h2[(size_t)B_ * H_];      //  8 MB

// ---------------------------------------------------------------------------
// Helpers
// ---------------------------------------------------------------------------
__device__ __forceinline__ uint32_t smem_u32(const void* p) {
    uint32_t a;
    asm("{ .reg .u64 t; cvta.to.shared.u64 t, %1; cvt.u32.u64 %0, t; }" : "=r"(a) : "l"(p));
    return a;
}

#define CPA16(sm, gp) \
    asm volatile("cp.async.cg.shared.global [%0], [%1], 16;" :: "r"(sm), "l"(gp) : "memory")
#define CP_COMMIT() asm volatile("cp.async.commit_group;" ::: "memory")
#define CP_WAIT0()  asm volatile("cp.async.wait_group 0;" ::: "memory")

__device__ __forceinline__ void fma2(u64& d, u64 a, u64 b) {
    asm("fma.rn.f32x2 %0, %1, %2, %0;" : "+l"(d) : "l"(a), "l"(b));
}
__device__ __forceinline__ float2 u2f(u64 v) {
    float2 f;
    f.x = __uint_as_float((unsigned)v);
    f.y = __uint_as_float((unsigned)(v >> 32));
    return f;
}
__device__ __forceinline__ u64 dupf(float v) {
    u64 b = (u64)__float_as_uint(v);
    return b | (b << 32);
}
__device__ __forceinline__ float lk(float v) { return v > 0.f ? v : 0.2f * v; }

// ---------------------------------------------------------------------------
// Init: D0/D1 = de-interleaved z; logdet = 0
// ---------------------------------------------------------------------------
__global__ void init_kernel(const float* __restrict__ z, float* __restrict__ logdet) {
    const int r = blockIdx.x;
    const int tid = threadIdx.x;
    const float* zrow = z + (size_t)r * N_;
#pragma unroll
    for (int c = tid; c < NM_; c += 256) {
        const int g = c >> 5, m = c & 31;
        g_D0[(size_t)r * NM_ + c] = zrow[g * 64 + 2 * m + (g & 1)];
        g_D1[(size_t)r * NM_ + c] = zrow[g * 64 + 2 * m + ((g + 1) & 1)];
    }
    if (tid == 0) logdet[r] = 0.0f;
}

// ---------------------------------------------------------------------------
// Final: interleave D0/D1 back into x
// ---------------------------------------------------------------------------
__global__ void merge_kernel(float* __restrict__ x) {
    const int r = blockIdx.x;
    const int tid = threadIdx.x;
    float* xrow = x + (size_t)r * N_;
    const float* d0 = g_D0 + (size_t)r * NM_;
    const float* d1 = g_D1 + (size_t)r * NM_;
#pragma unroll
    for (int cell = tid * 2; cell < N_; cell += 512) {
        const int g = cell >> 6, j = cell & 63;    // j even
        const int m = j >> 1;
        // cell  (j even): from D0 if g even else D1
        // cell+1(j odd) : from D1 if g even else D0
        float a = d0[(g << 5) + m], b = d1[(g << 5) + m];
        float2 v;
        if (g & 1) { v.x = b; v.y = a; }
        else       { v.x = a; v.y = b; }
        *(float2*)(xrow + cell) = v;
    }
}

// ---------------------------------------------------------------------------
// f32x2 SGEMM:  D[64 x 128] = A[64 x K_TOT] @ W-slice  (R6 tile config)
//   128 threads, 4 CTAs/SM, thread tile 8 rows x (4 + 4) cols.
//   ASEL: 0=g_D0 1=g_D1 2=g_p(+pair, ACOMB) 3=g_h2
//   MODE 2: store raw acc to g_p[blockIdx.z]   (GEMM1 K-split halves)
//   MODE 0: bias+leaky -> g_h2                 (GEMM2; ACOMB combines partials)
//   MODE 1: fused coupling update on dense updated half (usel) + logdet
// ---------------------------------------------------------------------------
template <int K_TOT, int ACOMB, int MODE>
__global__ void __launch_bounds__(128, 4)
gemm_f32x2(int asel, const float* __restrict__ abias, int lda,
           const float* __restrict__ W, int ldw,
           const float* __restrict__ bias,
           float* __restrict__ logdet, int usel) {
    __shared__ u64   As2[2][16][64];      // 16 KB (k-major, dup pairs)
    __shared__ float Bs[2][16][128];      // 16 KB

    const int tid  = threadIdx.x;
    const int row0 = blockIdx.y * 64;
    const int bx   = blockIdx.x;
    const int tRow = (tid >> 4) * 8;      // 0..56
    const int nOff = (tid & 15) * 4;      // 0..60
    constexpr int NS = K_TOT / 16;
    const int kbase = (MODE == 2) ? blockIdx.z * K_TOT : 0;

    const float* Ap0 = (asel == 0) ? g_D0 : (asel == 1) ? g_D1 : (asel == 2) ? g_p : g_h2;
    const float* Ap1 = g_p + (size_t)B_ * H_;     // only used when ACOMB
    Ap0 += (size_t)row0 * lda + kbase;
    if (ACOMB) Ap1 += (size_t)row0 * lda;
    const float* Wp = W + (size_t)kbase * ldw;

    const uint32_t bsBase = smem_u32(&Bs[0][0][0]);

    auto loadB = [&](int kt, int buf) {
#pragma unroll
        for (int i = 0; i < 4; i++) {
            const int ch = tid + i * 128;          // 0..511
            const int k  = ch >> 5;                // 0..15
            if (MODE == 1) {
                const int seg = (ch >> 4) & 1;
                const int c   = ch & 15;
                const int col = (seg ? 2048 + bx * 64 : bx * 64) + c * 4;
                const uint32_t so = bsBase + buf * 8192 + (k * 128 + seg * 64 + c * 4) * 4;
                CPA16(so, Wp + (size_t)(kt + k) * ldw + col);
            } else {
                const int c = ch & 31;
                const int col = bx * 128 + c * 4;
                const uint32_t so = bsBase + buf * 8192 + (k * 128 + c * 4) * 4;
                CPA16(so, Wp + (size_t)(kt + k) * ldw + col);
            }
        }
        CP_COMMIT();
    };

    // A loader: 64 rows x 4 float4-chunks = 256 chunks over 128 threads (2 each)
    auto loadA = [&](int kt, float4* ar) {
#pragma unroll
        for (int i = 0; i < 2; i++) {
            const int ch = tid + i * 128;
            const int row = ch >> 2, kq = ch & 3;
            const size_t off = (size_t)row * lda + kt + kq * 4;
            float4 a0 = *(const float4*)(Ap0 + off);
            if (ACOMB) {
                const float4 a1 = *(const float4*)(Ap1 + off);
                const float4 bb = *(const float4*)(abias + kt + kq * 4);
                a0.x = lk(a0.x + a1.x + bb.x);
                a0.y = lk(a0.y + a1.y + bb.y);
                a0.z = lk(a0.z + a1.z + bb.z);
                a0.w = lk(a0.w + a1.w + bb.w);
            }
            ar[i] = a0;
        }
    };
    auto storeA = [&](const float4* ar, int buf) {
#pragma unroll
        for (int i = 0; i < 2; i++) {
            const int ch = tid + i * 128;
            const int row = ch >> 2, kq = ch & 3;
            As2[buf][kq * 4 + 0][row] = dupf(ar[i].x);
            As2[buf][kq * 4 + 1][row] = dupf(ar[i].y);
            As2[buf][kq * 4 + 2][row] = dupf(ar[i].z);
            As2[buf][kq * 4 + 3][row] = dupf(ar[i].w);
        }
    };

    u64 acc[8][4];
#pragma unroll
    for (int i = 0; i < 8; i++)
#pragma unroll
        for (int j = 0; j < 4; j++) acc[i][j] = 0ULL;

    // ---- prologue ----
    {
        float4 ar[2];
        loadB(0, 0);
        loadA(0, ar);
        storeA(ar, 0);
        CP_WAIT0();
        __syncthreads();
    }

    // ---- main loop: one barrier per stage ----
    for (int c = 0; c < NS; c++) {
        float4 ar[2];
        const int nb = (c + 1) & 1;
        if (c + 1 < NS) {
            loadA((c + 1) * 16, ar);
            loadB((c + 1) * 16, nb);
        }
        {
            const int buf = c & 1;
#pragma unroll
            for (int k = 0; k < 16; k++) {
                u64 a[8];
#pragma unroll
                for (int i = 0; i < 4; i++) {
                    ulonglong2 av = *(const ulonglong2*)&As2[buf][k][tRow + 2 * i];
                    a[2 * i]     = av.x;
                    a[2 * i + 1] = av.y;
                }
                const ulonglong2 b0 = *(const ulonglong2*)&Bs[buf][k][nOff];
                const ulonglong2 b1 = *(const ulonglong2*)&Bs[buf][k][nOff + 64];
#pragma unroll
                for (int i = 0; i < 8; i++) {
                    fma2(acc[i][0], a[i], b0.x);
                    fma2(acc[i][1], a[i], b0.y);
                    fma2(acc[i][2], a[i], b1.x);
                    fma2(acc[i][3], a[i], b1.y);
                }
            }
        }
        if (c + 1 < NS) {
            storeA(ar, nb);
            CP_WAIT0();
        }
        __syncthreads();
    }

    // ---- epilogue ----
    if (MODE == 2) {
        // raw partial -> g_p[blockIdx.z]
        float* Out = g_p + (size_t)blockIdx.z * B_ * H_;
        const int c0 = bx * 128 + nOff;
        const int c1 = c0 + 64;
#pragma unroll
        for (int i = 0; i < 8; i++) {
            const int r = row0 + tRow + i;
            float2 p0 = u2f(acc[i][0]), p1 = u2f(acc[i][1]);
            float2 p2 = u2f(acc[i][2]), p3 = u2f(acc[i][3]);
            float4 v0, v1;
            v0.x = p0.x; v0.y = p0.y; v0.z = p1.x; v0.w = p1.y;
            v1.x = p2.x; v1.y = p2.y; v1.z = p3.x; v1.w = p3.y;
            *(float4*)(Out + (size_t)r * H_ + c0) = v0;
            *(float4*)(Out + (size_t)r * H_ + c1) = v1;
        }
    } else if (MODE == 0) {
        float* Out = g_h2;
        const int c0 = bx * 128 + nOff;
        const int c1 = c0 + 64;
        const float4 bl = *(const float4*)(bias + c0);
        const float4 bh = *(const float4*)(bias + c1);
#pragma unroll
        for (int i = 0; i < 8; i++) {
            const int r = row0 + tRow + i;
            float2 p0 = u2f(acc[i][0]), p1 = u2f(acc[i][1]);
            float2 p2 = u2f(acc[i][2]), p3 = u2f(acc[i][3]);
            float4 v0, v1;
            v0.x = lk(p0.x + bl.x); v0.y = lk(p0.y + bl.y);
            v0.z = lk(p1.x + bl.z); v0.w = lk(p1.y + bl.w);
            v1.x = lk(p2.x + bh.x); v1.y = lk(p2.y + bh.y);
            v1.z = lk(p3.x + bh.z); v1.w = lk(p3.y + bh.w);
            *(float4*)(Out + (size_t)r * H_ + c0) = v0;
            *(float4*)(Out + (size_t)r * H_ + c1) = v1;
        }
    } else {
        // fused coupling update on dense updated half (also next layer's A)
        float* U = usel ? g_D1 : g_D0;
        const int cs0 = bx * 64 + nOff;
        const float4 bs = *(const float4*)(bias + cs0);
        const float4 bt = *(const float4*)(bias + 2048 + cs0);
#pragma unroll
        for (int i = 0; i < 8; i++) {
            const int r = row0 + tRow + i;
            float* urow = U + (size_t)r * NM_ + cs0;
            const float4 old = *(const float4*)urow;
            float2 s01 = u2f(acc[i][0]), s23 = u2f(acc[i][1]);
            float2 t01 = u2f(acc[i][2]), t23 = u2f(acc[i][3]);
            const float sp[4] = { s01.x + bs.x, s01.y + bs.y, s23.x + bs.z, s23.y + bs.w };
            const float tp[4] = { t01.x + bt.x, t01.y + bt.y, t23.x + bt.z, t23.y + bt.w };
            const float ov[4] = { old.x, old.y, old.z, old.w };
            float nv[4], ssum = 0.0f;
#pragma unroll
            for (int q = 0; q < 4; q++) {
                const float e2u = __expf(2.0f * sp[q]);        // tanh via exp
                const float s   = 2.0f - 4.0f / (e2u + 1.0f);  // 2*tanh(sp)
                nv[q] = ov[q] * __expf(s) + tp[q];
                ssum += s;
            }
            float4 w;
            w.x = nv[0]; w.y = nv[1]; w.z = nv[2]; w.w = nv[3];
            *(float4*)urow = w;
            ssum += __shfl_xor_sync(0xffffffffu, ssum, 1);
            ssum += __shfl_xor_sync(0xffffffffu, ssum, 2);
            ssum += __shfl_xor_sync(0xffffffffu, ssum, 4);
            ssum += __shfl_xor_sync(0xffffffffu, ssum, 8);
            if ((tid & 15) == 0) atomicAdd(&logdet[r], ssum);
        }
    }
}

// ---------------------------------------------------------------------------
// Launch
// ---------------------------------------------------------------------------
extern "C" void kernel_launch(void* const* d_in, const int* in_sizes, int n_in,
                              void* d_out, int out_size) {
    const float* z  = (const float*)d_in[0];
    const float* W1 = (const float*)d_in[1];
    const float* b1 = (const float*)d_in[2];
    const float* W2 = (const float*)d_in[3];
    const float* b2 = (const float*)d_in[4];
    const float* W3 = (const float*)d_in[5];
    const float* b3 = (const float*)d_in[6];

    float* x      = (float*)d_out;
    float* logdet = x + (size_t)B_ * N_;

    init_kernel<<<B_, 256>>>(z, logdet);

    for (int l = 0; l < NLAY_; l++) {
        const int p = l & 1;
        const float* w1 = W1 + (size_t)l * NM_ * H_;
        const float* w2 = W2 + (size_t)l * H_ * H_;
        const float* w3 = W3 + (size_t)l * H_ * N_;
        const int masked  = p;        // 0 -> D0 masked, 1 -> D1 masked
        const int updated = p ^ 1;    // the other half

        // GEMM1 (K-split x2): partials p_z = Msk @ W1[z-half]      512 CTAs
        gemm_f32x2<NM_ / 2, 0, 2><<<dim3(2, B_ / 64, 2), 128>>>(
            masked, nullptr, NM_, w1, H_, nullptr, nullptr, 0);
        // GEMM2: h2 = leaky( leaky(p0+p1+b1) @ W2 + b2 )           256 CTAs
        gemm_f32x2<H_, 1, 0><<<dim3(2, B_ / 64), 128>>>(
            2, b1 + (size_t)l * H_, H_, w2, H_, b2 + (size_t)l * H_, nullptr, 0);
        // GEMM3 fused: st = h2 @ W3 + b3 ; dense coupling update   4096 CTAs
        gemm_f32x2<H_, 0, 1><<<dim3(32, B_ / 64), 128>>>(
            3, nullptr, H_, w3, N_, b3 + (size_t)l * N_, logdet, updated);
    }

    merge_kernel<<<B_, 256>>>(x);
}

// round 11
// speedup vs baseline: 1.1993x; 1.0038x over previous
#include <cuda_runtime.h>
#include <cstdint>
#include <math.h>

#define B_   8192
#define N_   4096
#define H_   256
#define NM_  2048
#define NLAY_ 8

typedef unsigned long long u64;

// ---------------------------------------------------------------------------
// Scratch (static device globals — no allocation)
// Dense checkerboard halves: D0 = cells with (i+j) even, D1 = odd.
// ---------------------------------------------------------------------------
__device__ __align__(256) float g_D0[(size_t)B_ * NM_];     // 64 MB
__device__ __align__(256) float g_D1[(size_t)B_ * NM_];     // 64 MB
__device__ __align__(256) float g_p [2 * (size_t)B_ * H_];  // 16 MB GEMM1 K-split partials
__device__ __align__(256) float g_h2[(size_t)B_ * H_];      //  8 MB

// ---------------------------------------------------------------------------
// Helpers
// ---------------------------------------------------------------------------
__device__ __forceinline__ uint32_t smem_u32(const void* p) {
    uint32_t a;
    asm("{ .reg .u64 t; cvta.to.shared.u64 t, %1; cvt.u32.u64 %0, t; }" : "=r"(a) : "l"(p));
    return a;
}

#define CPA16(sm, gp) \
    asm volatile("cp.async.cg.shared.global [%0], [%1], 16;" :: "r"(sm), "l"(gp) : "memory")
#define CP_COMMIT() asm volatile("cp.async.commit_group;" ::: "memory")
#define CP_WAIT1()  asm volatile("cp.async.wait_group 1;" ::: "memory")

__device__ __forceinline__ void fma2(u64& d, u64 a, u64 b) {
    asm("fma.rn.f32x2 %0, %1, %2, %0;" : "+l"(d) : "l"(a), "l"(b));
}
__device__ __forceinline__ float2 u2f(u64 v) {
    float2 f;
    f.x = __uint_as_float((unsigned)v);
    f.y = __uint_as_float((unsigned)(v >> 32));
    return f;
}
__device__ __forceinline__ u64 dupf(float v) {
    u64 b = (u64)__float_as_uint(v);
    return b | (b << 32);
}
__device__ __forceinline__ float lk(float v) { return v > 0.f ? v : 0.2f * v; }

// ---------------------------------------------------------------------------
// Init: D0/D1 = de-interleaved z; logdet = 0
// ---------------------------------------------------------------------------
__global__ void init_kernel(const float* __restrict__ z, float* __restrict__ logdet) {
    const int r = blockIdx.x;
    const int tid = threadIdx.x;
    const float* zrow = z + (size_t)r * N_;
#pragma unroll
    for (int c = tid; c < NM_; c += 256) {
        const int g = c >> 5, m = c & 31;
        g_D0[(size_t)r * NM_ + c] = zrow[g * 64 + 2 * m + (g & 1)];
        g_D1[(size_t)r * NM_ + c] = zrow[g * 64 + 2 * m + ((g + 1) & 1)];
    }
    if (tid == 0) logdet[r] = 0.0f;
}

// ---------------------------------------------------------------------------
// Final: interleave D0/D1 back into x
// ---------------------------------------------------------------------------
__global__ void merge_kernel(float* __restrict__ x) {
    const int r = blockIdx.x;
    const int tid = threadIdx.x;
    float* xrow = x + (size_t)r * N_;
    const float* d0 = g_D0 + (size_t)r * NM_;
    const float* d1 = g_D1 + (size_t)r * NM_;
#pragma unroll
    for (int cell = tid * 2; cell < N_; cell += 512) {
        const int g = cell >> 6, j = cell & 63;
        const int m = j >> 1;
        float a = d0[(g << 5) + m], b = d1[(g << 5) + m];
        float2 v;
        if (g & 1) { v.x = b; v.y = a; }
        else       { v.x = a; v.y = b; }
        *(float2*)(xrow + cell) = v;
    }
}

// ---------------------------------------------------------------------------
// f32x2 SGEMM:  D[64 x 128] = A[64 x K_TOT] @ W-slice
//   128 threads, 4 CTAs/SM, thread tile 8 rows x (4 + 4) cols.
//   A: 2-stage (regs->STS dup-pairs).  B: 3-stage cp.async ring, wait_group 1.
//   ASEL: 0=g_D0 1=g_D1 2=g_p(+pair, ACOMB) 3=g_h2
//   MODE 2: raw acc -> g_p[blockIdx.z]   (GEMM1 K-split halves)
//   MODE 0: bias+leaky -> g_h2           (GEMM2; ACOMB combines partials)
//   MODE 1: fused coupling update on dense updated half (usel) + logdet
// ---------------------------------------------------------------------------
template <int K_TOT, int ACOMB, int MODE>
__global__ void __launch_bounds__(128, 4)
gemm_f32x2(int asel, const float* __restrict__ abias, int lda,
           const float* __restrict__ W, int ldw,
           const float* __restrict__ bias,
           float* __restrict__ logdet, int usel) {
    __shared__ u64   As2[2][16][64];      // 16 KB (k-major, dup pairs)
    __shared__ float Bs[3][16][128];      // 24 KB (3-stage ring)

    const int tid  = threadIdx.x;
    const int row0 = blockIdx.y * 64;
    const int bx   = blockIdx.x;
    const int tRow = (tid >> 4) * 8;      // 0..56
    const int nOff = (tid & 15) * 4;      // 0..60
    constexpr int NS = K_TOT / 16;
    const int kbase = (MODE == 2) ? blockIdx.z * K_TOT : 0;

    const float* Ap0 = (asel == 0) ? g_D0 : (asel == 1) ? g_D1 : (asel == 2) ? g_p : g_h2;
    const float* Ap1 = g_p + (size_t)B_ * H_;     // only used when ACOMB
    Ap0 += (size_t)row0 * lda + kbase;
    if (ACOMB) Ap1 += (size_t)row0 * lda;
    const float* Wp = W + (size_t)kbase * ldw;

    const uint32_t bsBase = smem_u32(&Bs[0][0][0]);

    // B stage loader: 8KB, 4 cp.async/thread. Always commits (empty ok).
    auto issueB = [&](int stage) {
        if (stage < NS) {
            const int buf = stage % 3;
            const int kt = stage * 16;
#pragma unroll
            for (int i = 0; i < 4; i++) {
                const int ch = tid + i * 128;          // 0..511
                const int k  = ch >> 5;                // 0..15
                if (MODE == 1) {
                    const int seg = (ch >> 4) & 1;
                    const int c   = ch & 15;
                    const int col = (seg ? 2048 + bx * 64 : bx * 64) + c * 4;
                    const uint32_t so = bsBase + buf * 8192 + (k * 128 + seg * 64 + c * 4) * 4;
                    CPA16(so, Wp + (size_t)(kt + k) * ldw + col);
                } else {
                    const int c = ch & 31;
                    const int col = bx * 128 + c * 4;
                    const uint32_t so = bsBase + buf * 8192 + (k * 128 + c * 4) * 4;
                    CPA16(so, Wp + (size_t)(kt + k) * ldw + col);
                }
            }
        }
        CP_COMMIT();
    };

    // A: 64 rows x 4 float4-chunks = 256 chunks over 128 threads (2 each)
    auto loadA = [&](int kt, float4* ar) {
#pragma unroll
        for (int i = 0; i < 2; i++) {
            const int ch = tid + i * 128;
            const int row = ch >> 2, kq = ch & 3;
            const size_t off = (size_t)row * lda + kt + kq * 4;
            float4 a0 = *(const float4*)(Ap0 + off);
            if (ACOMB) {
                const float4 a1 = *(const float4*)(Ap1 + off);
                const float4 bb = *(const float4*)(abias + kt + kq * 4);
                a0.x = lk(a0.x + a1.x + bb.x);
                a0.y = lk(a0.y + a1.y + bb.y);
                a0.z = lk(a0.z + a1.z + bb.z);
                a0.w = lk(a0.w + a1.w + bb.w);
            }
            ar[i] = a0;
        }
    };
    auto storeA = [&](const float4* ar, int buf) {
#pragma unroll
        for (int i = 0; i < 2; i++) {
            const int ch = tid + i * 128;
            const int row = ch >> 2, kq = ch & 3;
            As2[buf][kq * 4 + 0][row] = dupf(ar[i].x);
            As2[buf][kq * 4 + 1][row] = dupf(ar[i].y);
            As2[buf][kq * 4 + 2][row] = dupf(ar[i].z);
            As2[buf][kq * 4 + 3][row] = dupf(ar[i].w);
        }
    };

    u64 acc[8][4];
#pragma unroll
    for (int i = 0; i < 8; i++)
#pragma unroll
        for (int j = 0; j < 4; j++) acc[i][j] = 0ULL;

    // ---- prologue: B stages 0,1 in flight; A stage 0 staged ----
    {
        float4 ar[2];
        issueB(0);
        issueB(1);
        loadA(0, ar);
        storeA(ar, 0);
        CP_WAIT1();           // group 0 (B stage 0) complete
        __syncthreads();
    }

    // ---- main loop: one barrier per stage ----
    for (int c = 0; c < NS; c++) {
        float4 ar[2];
        if (c + 1 < NS) loadA((c + 1) * 16, ar);
        issueB(c + 2);        // commit always (empty at tail)
        {
            const int abuf = c & 1;
            const int bbuf = c % 3;
#pragma unroll
            for (int k = 0; k < 16; k++) {
                u64 a[8];
#pragma unroll
                for (int i = 0; i < 4; i++) {
                    ulonglong2 av = *(const ulonglong2*)&As2[abuf][k][tRow + 2 * i];
                    a[2 * i]     = av.x;
                    a[2 * i + 1] = av.y;
                }
                const ulonglong2 b0 = *(const ulonglong2*)&Bs[bbuf][k][nOff];
                const ulonglong2 b1 = *(const ulonglong2*)&Bs[bbuf][k][nOff + 64];
#pragma unroll
                for (int i = 0; i < 8; i++) {
                    fma2(acc[i][0], a[i], b0.x);
                    fma2(acc[i][1], a[i], b0.y);
                    fma2(acc[i][2], a[i], b1.x);
                    fma2(acc[i][3], a[i], b1.y);
                }
            }
        }
        if (c + 1 < NS) storeA(ar, (c + 1) & 1);
        CP_WAIT1();           // B stage c+1 complete (all but newest group)
        __syncthreads();
    }

    // ---- epilogue ----
    if (MODE == 2) {
        float* Out = g_p + (size_t)blockIdx.z * B_ * H_;
        const int c0 = bx * 128 + nOff;
        const int c1 = c0 + 64;
#pragma unroll
        for (int i = 0; i < 8; i++) {
            const int r = row0 + tRow + i;
            float2 p0 = u2f(acc[i][0]), p1 = u2f(acc[i][1]);
            float2 p2 = u2f(acc[i][2]), p3 = u2f(acc[i][3]);
            float4 v0, v1;
            v0.x = p0.x; v0.y = p0.y; v0.z = p1.x; v0.w = p1.y;
            v1.x = p2.x; v1.y = p2.y; v1.z = p3.x; v1.w = p3.y;
            *(float4*)(Out + (size_t)r * H_ + c0) = v0;
            *(float4*)(Out + (size_t)r * H_ + c1) = v1;
        }
    } else if (MODE == 0) {
        float* Out = g_h2;
        const int c0 = bx * 128 + nOff;
        const int c1 = c0 + 64;
        const float4 bl = *(const float4*)(bias + c0);
        const float4 bh = *(const float4*)(bias + c1);
#pragma unroll
        for (int i = 0; i < 8; i++) {
            const int r = row0 + tRow + i;
            float2 p0 = u2f(acc[i][0]), p1 = u2f(acc[i][1]);
            float2 p2 = u2f(acc[i][2]), p3 = u2f(acc[i][3]);
            float4 v0, v1;
            v0.x = lk(p0.x + bl.x); v0.y = lk(p0.y + bl.y);
            v0.z = lk(p1.x + bl.z); v0.w = lk(p1.y + bl.w);
            v1.x = lk(p2.x + bh.x); v1.y = lk(p2.y + bh.y);
            v1.z = lk(p3.x + bh.z); v1.w = lk(p3.y + bh.w);
            *(float4*)(Out + (size_t)r * H_ + c0) = v0;
            *(float4*)(Out + (size_t)r * H_ + c1) = v1;
        }
    } else {
        // fused coupling update on dense updated half (also next layer's A)
        float* U = usel ? g_D1 : g_D0;
        const int cs0 = bx * 64 + nOff;
        const float4 bs = *(const float4*)(bias + cs0);
        const float4 bt = *(const float4*)(bias + 2048 + cs0);
        // per-(row, thread-col-group) partial sums staged in smem
        float* sred = (float*)&As2[0][0][0];    // 64 rows x 16 groups (4 KB)
#pragma unroll
        for (int i = 0; i < 8; i++) {
            const int rl = tRow + i;
            const int r = row0 + rl;
            float* urow = U + (size_t)r * NM_ + cs0;
            const float4 old = *(const float4*)urow;
            float2 s01 = u2f(acc[i][0]), s23 = u2f(acc[i][1]);
            float2 t01 = u2f(acc[i][2]), t23 = u2f(acc[i][3]);
            const float sp[4] = { s01.x + bs.x, s01.y + bs.y, s23.x + bs.z, s23.y + bs.w };
            const float tp[4] = { t01.x + bt.x, t01.y + bt.y, t23.x + bt.z, t23.y + bt.w };
            const float ov[4] = { old.x, old.y, old.z, old.w };
            float nv[4], ssum = 0.0f;
#pragma unroll
            for (int q = 0; q < 4; q++) {
                const float e2u = __expf(2.0f * sp[q]);        // tanh via exp
                const float s   = 2.0f - 4.0f / (e2u + 1.0f);  // 2*tanh(sp)
                nv[q] = ov[q] * __expf(s) + tp[q];
                ssum += s;
            }
            float4 w;
            w.x = nv[0]; w.y = nv[1]; w.z = nv[2]; w.w = nv[3];
            *(float4*)urow = w;
            sred[rl * 16 + (tid & 15)] = ssum;
        }
        __syncthreads();
        // 64 rows: threads 0..63 reduce 16 partials each
        if (tid < 64) {
            float acc_s = 0.0f;
#pragma unroll
            for (int qq = 0; qq < 16; qq++) acc_s += sred[tid * 16 + qq];
            atomicAdd(&logdet[row0 + tid], acc_s);
        }
    }
}

// ---------------------------------------------------------------------------
// Launch
// ---------------------------------------------------------------------------
extern "C" void kernel_launch(void* const* d_in, const int* in_sizes, int n_in,
                              void* d_out, int out_size) {
    const float* z  = (const float*)d_in[0];
    const float* W1 = (const float*)d_in[1];
    const float* b1 = (const float*)d_in[2];
    const float* W2 = (const float*)d_in[3];
    const float* b2 = (const float*)d_in[4];
    const float* W3 = (const float*)d_in[5];
    const float* b3 = (const float*)d_in[6];

    float* x      = (float*)d_out;
    float* logdet = x + (size_t)B_ * N_;

    init_kernel<<<B_, 256>>>(z, logdet);

    for (int l = 0; l < NLAY_; l++) {
        const int p = l & 1;
        const float* w1 = W1 + (size_t)l * NM_ * H_;
        const float* w2 = W2 + (size_t)l * H_ * H_;
        const float* w3 = W3 + (size_t)l * H_ * N_;
        const int masked  = p;
        const int updated = p ^ 1;

        // GEMM1 (K-split x2): partials = Msk @ W1[z-half]          512 CTAs
        gemm_f32x2<NM_ / 2, 0, 2><<<dim3(2, B_ / 64, 2), 128>>>(
            masked, nullptr, NM_, w1, H_, nullptr, nullptr, 0);
        // GEMM2: h2 = leaky( leaky(p0+p1+b1) @ W2 + b2 )           256 CTAs
        gemm_f32x2<H_, 1, 0><<<dim3(2, B_ / 64), 128>>>(
            2, b1 + (size_t)l * H_, H_, w2, H_, b2 + (size_t)l * H_, nullptr, 0);
        // GEMM3 fused: st = h2 @ W3 + b3 ; dense coupling update   4096 CTAs
        gemm_f32x2<H_, 0, 1><<<dim3(32, B_ / 64), 128>>>(
            3, nullptr, H_, w3, N_, b3 + (size_t)l * N_, logdet, updated);
    }

    merge_kernel<<<B_, 256>>>(x);
}

// round 13
// speedup vs baseline: 1.5373x; 1.2818x over previous
#include <cuda_runtime.h>
#include <cstdint>
#include <math.h>

#define B_   8192
#define N_   4096
#define H_   256
#define NM_  2048
#define NLAY_ 8

typedef unsigned long long u64;

// ---------------------------------------------------------------------------
// Scratch (static device globals — no allocation)
// Dense checkerboard halves: D0 = cells with (i+j) even, D1 = odd.
// ---------------------------------------------------------------------------
__device__ __align__(256) float g_D0[(size_t)B_ * NM_];     // 64 MB
__device__ __align__(256) float g_D1[(size_t)B_ * NM_];     // 64 MB
__device__ __align__(256) float g_p [2 * (size_t)B_ * H_];  // 16 MB GEMM1 K-split partials
__device__ __align__(256) float g_h2[(size_t)B_ * H_];      //  8 MB

// ---------------------------------------------------------------------------
// Helpers
// ---------------------------------------------------------------------------
__device__ __forceinline__ uint32_t smem_u32(const void* p) {
    uint32_t a;
    asm("{ .reg .u64 t; cvta.to.shared.u64 t, %1; cvt.u32.u64 %0, t; }" : "=r"(a) : "l"(p));
    return a;
}

#define CPA16(sm, gp) \
    asm volatile("cp.async.cg.shared.global [%0], [%1], 16;" :: "r"(sm), "l"(gp) : "memory")
#define CP_COMMIT() asm volatile("cp.async.commit_group;" ::: "memory")
#define CP_WAIT1()  asm volatile("cp.async.wait_group 1;" ::: "memory")

__device__ __forceinline__ void fma2(u64& d, u64 a, u64 b) {
    asm("fma.rn.f32x2 %0, %1, %2, %0;" : "+l"(d) : "l"(a), "l"(b));
}
__device__ __forceinline__ float2 u2f(u64 v) {
    float2 f;
    f.x = __uint_as_float((unsigned)v);
    f.y = __uint_as_float((unsigned)(v >> 32));
    return f;
}
// single-instruction register dup {f,f}
__device__ __forceinline__ u64 dupr(float f) {
    u64 d;
    asm("mov.b64 %0, {%1, %1};" : "=l"(d) : "f"(f));
    return d;
}
__device__ __forceinline__ float lk(float v) { return v > 0.f ? v : 0.2f * v; }

// ---------------------------------------------------------------------------
// Init: D0/D1 = de-interleaved z; logdet = 0
// ---------------------------------------------------------------------------
__global__ void init_kernel(const float* __restrict__ z, float* __restrict__ logdet) {
    const int r = blockIdx.x;
    const int tid = threadIdx.x;
    const float* zrow = z + (size_t)r * N_;
#pragma unroll
    for (int c = tid; c < NM_; c += 256) {
        const int g = c >> 5, m = c & 31;
        g_D0[(size_t)r * NM_ + c] = zrow[g * 64 + 2 * m + (g & 1)];
        g_D1[(size_t)r * NM_ + c] = zrow[g * 64 + 2 * m + ((g + 1) & 1)];
    }
    if (tid == 0) logdet[r] = 0.0f;
}

// ---------------------------------------------------------------------------
// Final: interleave D0/D1 back into x
// ---------------------------------------------------------------------------
__global__ void merge_kernel(float* __restrict__ x) {
    const int r = blockIdx.x;
    const int tid = threadIdx.x;
    float* xrow = x + (size_t)r * N_;
    const float* d0 = g_D0 + (size_t)r * NM_;
    const float* d1 = g_D1 + (size_t)r * NM_;
#pragma unroll
    for (int cell = tid * 2; cell < N_; cell += 512) {
        const int g = cell >> 6, j = cell & 63;
        const int m = j >> 1;
        float a = d0[(g << 5) + m], b = d1[(g << 5) + m];
        float2 v;
        if (g & 1) { v.x = b; v.y = a; }
        else       { v.x = a; v.y = b; }
        *(float2*)(xrow + cell) = v;
    }
}

// ---------------------------------------------------------------------------
// f32x2 SGEMM:  D[64 x 128] = A[64 x K_TOT] @ W-slice
//   128 threads, 4 CTAs/SM, thread tile 8 rows x (4 + 4) cols.
//   Row-pair packing: A natural float2 pairs from plain smem (2 LDS.128/k),
//   B loaded as float4 (2 LDS.128/k) and duplicated in registers (mov.b64).
//   ASEL: 0=g_D0 1=g_D1 2=g_p(+pair, ACOMB) 3=g_h2
//   MODE 2: raw acc -> g_p[blockIdx.z]   (GEMM1 K-split halves)
//   MODE 0: bias+leaky -> g_h2           (GEMM2; ACOMB combines partials)
//   MODE 1: fused coupling update on dense updated half (usel) + logdet
// ---------------------------------------------------------------------------
template <int K_TOT, int ACOMB, int MODE>
__global__ void __launch_bounds__(128, 4)
gemm_f32x2(int asel, const float* __restrict__ abias, int lda,
           const float* __restrict__ W, int ldw,
           const float* __restrict__ bias,
           float* __restrict__ logdet, int usel) {
    __shared__ float As[2][16][64];       //  8 KB (k-major, plain floats)
    __shared__ float Bs[3][16][128];      // 24 KB (3-stage ring)

    const int tid  = threadIdx.x;
    const int row0 = blockIdx.y * 64;
    const int bx   = blockIdx.x;
    const int tRow = (tid >> 4) * 8;      // 0..56
    const int nOff = (tid & 15) * 4;      // 0..60
    constexpr int NS = K_TOT / 16;
    const int kbase = (MODE == 2) ? blockIdx.z * K_TOT : 0;

    const float* Ap0 = (asel == 0) ? g_D0 : (asel == 1) ? g_D1 : (asel == 2) ? g_p : g_h2;
    const float* Ap1 = g_p + (size_t)B_ * H_;     // only used when ACOMB
    Ap0 += (size_t)row0 * lda + kbase;
    if (ACOMB) Ap1 += (size_t)row0 * lda;
    const float* Wp = W + (size_t)kbase * ldw;

    const uint32_t bsBase = smem_u32(&Bs[0][0][0]);

    // B stage loader: 8KB, 4 cp.async/thread. Always commits (empty ok).
    auto issueB = [&](int stage) {
        if (stage < NS) {
            const int buf = stage % 3;
            const int kt = stage * 16;
#pragma unroll
            for (int i = 0; i < 4; i++) {
                const int ch = tid + i * 128;          // 0..511
                const int k  = ch >> 5;                // 0..15
                if (MODE == 1) {
                    const int seg = (ch >> 4) & 1;
                    const int c   = ch & 15;
                    const int col = (seg ? 2048 + bx * 64 : bx * 64) + c * 4;
                    const uint32_t so = bsBase + buf * 8192 + (k * 128 + seg * 64 + c * 4) * 4;
                    CPA16(so, Wp + (size_t)(kt + k) * ldw + col);
                } else {
                    const int c = ch & 31;
                    const int col = bx * 128 + c * 4;
                    const uint32_t so = bsBase + buf * 8192 + (k * 128 + c * 4) * 4;
                    CPA16(so, Wp + (size_t)(kt + k) * ldw + col);
                }
            }
        }
        CP_COMMIT();
    };

    // A: 64 rows x 4 float4-chunks = 256 chunks over 128 threads (2 each)
    auto loadA = [&](int kt, float4* ar) {
#pragma unroll
        for (int i = 0; i < 2; i++) {
            const int ch = tid + i * 128;
            const int row = ch >> 2, kq = ch & 3;
            const size_t off = (size_t)row * lda + kt + kq * 4;
            float4 a0 = *(const float4*)(Ap0 + off);
            if (ACOMB) {
                const float4 a1 = *(const float4*)(Ap1 + off);
                const float4 bb = *(const float4*)(abias + kt + kq * 4);
                a0.x = lk(a0.x + a1.x + bb.x);
                a0.y = lk(a0.y + a1.y + bb.y);
                a0.z = lk(a0.z + a1.z + bb.z);
                a0.w = lk(a0.w + a1.w + bb.w);
            }
            ar[i] = a0;
        }
    };
    auto storeA = [&](const float4* ar, int buf) {
#pragma unroll
        for (int i = 0; i < 2; i++) {
            const int ch = tid + i * 128;
            const int row = ch >> 2, kq = ch & 3;
            As[buf][kq * 4 + 0][row] = ar[i].x;
            As[buf][kq * 4 + 1][row] = ar[i].y;
            As[buf][kq * 4 + 2][row] = ar[i].z;
            As[buf][kq * 4 + 3][row] = ar[i].w;
        }
    };

    // acc[i][j]: row-pair i (rows tRow+2i, tRow+2i+1), col j (0-3: nOff+, 4-7: nOff+64+)
    u64 acc[4][8];
#pragma unroll
    for (int i = 0; i < 4; i++)
#pragma unroll
        for (int j = 0; j < 8; j++) acc[i][j] = 0ULL;

    // ---- prologue: B stages 0,1 in flight; A stage 0 staged ----
    {
        float4 ar[2];
        issueB(0);
        issueB(1);
        loadA(0, ar);
        storeA(ar, 0);
        CP_WAIT1();           // B stage 0 complete
        __syncthreads();
    }

    // ---- main loop: one barrier per stage ----
    for (int c = 0; c < NS; c++) {
        float4 ar[2];
        if (c + 1 < NS) loadA((c + 1) * 16, ar);
        issueB(c + 2);        // commit always (empty at tail)
        {
            const int abuf = c & 1;
            const int bbuf = c % 3;
#pragma unroll
            for (int k = 0; k < 16; k++) {
                // A: natural row pairs, 2 x LDS.128 (broadcast across 16 threads)
                ulonglong2 av0 = *(const ulonglong2*)&As[abuf][k][tRow];
                ulonglong2 av1 = *(const ulonglong2*)&As[abuf][k][tRow + 4];
                u64 a[4];
                a[0] = av0.x; a[1] = av0.y; a[2] = av1.x; a[3] = av1.y;
                // B: 2 x LDS.128, dup in registers
                const float4 b0 = *(const float4*)&Bs[bbuf][k][nOff];
                const float4 b1 = *(const float4*)&Bs[bbuf][k][nOff + 64];
                u64 bd[8];
                bd[0] = dupr(b0.x); bd[1] = dupr(b0.y);
                bd[2] = dupr(b0.z); bd[3] = dupr(b0.w);
                bd[4] = dupr(b1.x); bd[5] = dupr(b1.y);
                bd[6] = dupr(b1.z); bd[7] = dupr(b1.w);
#pragma unroll
                for (int i = 0; i < 4; i++) {
#pragma unroll
                    for (int j = 0; j < 8; j++) fma2(acc[i][j], a[i], bd[j]);
                }
            }
        }
        if (c + 1 < NS) storeA(ar, (c + 1) & 1);
        CP_WAIT1();           // B stage c+1 complete
        __syncthreads();
    }

    // ---- epilogue ----
    if (MODE == 2) {
        float* Out = g_p + (size_t)blockIdx.z * B_ * H_;
        const int c0 = bx * 128 + nOff;
        const int c1 = c0 + 64;
#pragma unroll
        for (int i = 0; i < 4; i++) {
            float2 pj[8];
#pragma unroll
            for (int j = 0; j < 8; j++) pj[j] = u2f(acc[i][j]);
#pragma unroll
            for (int h = 0; h < 2; h++) {
                const int r = row0 + tRow + 2 * i + h;
                float4 v0, v1;
                v0.x = h ? pj[0].y : pj[0].x; v0.y = h ? pj[1].y : pj[1].x;
                v0.z = h ? pj[2].y : pj[2].x; v0.w = h ? pj[3].y : pj[3].x;
                v1.x = h ? pj[4].y : pj[4].x; v1.y = h ? pj[5].y : pj[5].x;
                v1.z = h ? pj[6].y : pj[6].x; v1.w = h ? pj[7].y : pj[7].x;
                *(float4*)(Out + (size_t)r * H_ + c0) = v0;
                *(float4*)(Out + (size_t)r * H_ + c1) = v1;
            }
        }
    } else if (MODE == 0) {
        float* Out = g_h2;
        const int c0 = bx * 128 + nOff;
        const int c1 = c0 + 64;
        const float4 bl = *(const float4*)(bias + c0);
        const float4 bh = *(const float4*)(bias + c1);
#pragma unroll
        for (int i = 0; i < 4; i++) {
            float2 pj[8];
#pragma unroll
            for (int j = 0; j < 8; j++) pj[j] = u2f(acc[i][j]);
#pragma unroll
            for (int h = 0; h < 2; h++) {
                const int r = row0 + tRow + 2 * i + h;
                float4 v0, v1;
                v0.x = lk((h ? pj[0].y : pj[0].x) + bl.x);
                v0.y = lk((h ? pj[1].y : pj[1].x) + bl.y);
                v0.z = lk((h ? pj[2].y : pj[2].x) + bl.z);
                v0.w = lk((h ? pj[3].y : pj[3].x) + bl.w);
                v1.x = lk((h ? pj[4].y : pj[4].x) + bh.x);
                v1.y = lk((h ? pj[5].y : pj[5].x) + bh.y);
                v1.z = lk((h ? pj[6].y : pj[6].x) + bh.z);
                v1.w = lk((h ? pj[7].y : pj[7].x) + bh.w);
                *(float4*)(Out + (size_t)r * H_ + c0) = v0;
                *(float4*)(Out + (size_t)r * H_ + c1) = v1;
            }
        }
    } else {
        // fused coupling update on dense updated half (also next layer's A)
        float* U = usel ? g_D1 : g_D0;
        const int cs0 = bx * 64 + nOff;
        const float4 bs = *(const float4*)(bias + cs0);
        const float4 bt = *(const float4*)(bias + 2048 + cs0);
        float* sred = (float*)&As[0][0][0];    // 64 rows x 16 groups (4 KB)
#pragma unroll
        for (int i = 0; i < 4; i++) {
            float2 pj[8];
#pragma unroll
            for (int j = 0; j < 8; j++) pj[j] = u2f(acc[i][j]);
#pragma unroll
            for (int h = 0; h < 2; h++) {
                const int rl = tRow + 2 * i + h;
                const int r = row0 + rl;
                float* urow = U + (size_t)r * NM_ + cs0;
                const float4 old = *(const float4*)urow;
                const float sp[4] = {
                    (h ? pj[0].y : pj[0].x) + bs.x, (h ? pj[1].y : pj[1].x) + bs.y,
                    (h ? pj[2].y : pj[2].x) + bs.z, (h ? pj[3].y : pj[3].x) + bs.w };
                const float tp[4] = {
                    (h ? pj[4].y : pj[4].x) + bt.x, (h ? pj[5].y : pj[5].x) + bt.y,
                    (h ? pj[6].y : pj[6].x) + bt.z, (h ? pj[7].y : pj[7].x) + bt.w };
                const float ov[4] = { old.x, old.y, old.z, old.w };
                float nv[4], ssum = 0.0f;
#pragma unroll
                for (int q = 0; q < 4; q++) {
                    const float e2u = __expf(2.0f * sp[q]);        // tanh via exp
                    const float s   = 2.0f - 4.0f / (e2u + 1.0f);  // 2*tanh(sp)
                    nv[q] = ov[q] * __expf(s) + tp[q];
                    ssum += s;
                }
                float4 w;
                w.x = nv[0]; w.y = nv[1]; w.z = nv[2]; w.w = nv[3];
                *(float4*)urow = w;
                sred[rl * 16 + (tid & 15)] = ssum;
            }
        }
        __syncthreads();
        if (tid < 64) {
            float acc_s = 0.0f;
#pragma unroll
            for (int qq = 0; qq < 16; qq++) acc_s += sred[tid * 16 + qq];
            atomicAdd(&logdet[row0 + tid], acc_s);
        }
    }
}

// ---------------------------------------------------------------------------
// Launch
// ---------------------------------------------------------------------------
extern "C" void kernel_launch(void* const* d_in, const int* in_sizes, int n_in,
                              void* d_out, int out_size) {
    const float* z  = (const float*)d_in[0];
    const float* W1 = (const float*)d_in[1];
    const float* b1 = (const float*)d_in[2];
    const float* W2 = (const float*)d_in[3];
    const float* b2 = (const float*)d_in[4];
    const float* W3 = (const float*)d_in[5];
    const float* b3 = (const float*)d_in[6];

    float* x      = (float*)d_out;
    float* logdet = x + (size_t)B_ * N_;

    init_kernel<<<B_, 256>>>(z, logdet);

    for (int l = 0; l < NLAY_; l++) {
        const int p = l & 1;
        const float* w1 = W1 + (size_t)l * NM_ * H_;
        const float* w2 = W2 + (size_t)l * H_ * H_;
        const float* w3 = W3 + (size_t)l * H_ * N_;
        const int masked  = p;
        const int updated = p ^ 1;

        // GEMM1 (K-split x2): partials = Msk @ W1[z-half]          512 CTAs
        gemm_f32x2<NM_ / 2, 0, 2><<<dim3(2, B_ / 64, 2), 128>>>(
            masked, nullptr, NM_, w1, H_, nullptr, nullptr, 0);
        // GEMM2: h2 = leaky( leaky(p0+p1+b1) @ W2 + b2 )           256 CTAs
        gemm_f32x2<H_, 1, 0><<<dim3(2, B_ / 64), 128>>>(
            2, b1 + (size_t)l * H_, H_, w2, H_, b2 + (size_t)l * H_, nullptr, 0);
        // GEMM3 fused: st = h2 @ W3 + b3 ; dense coupling update   4096 CTAs
        gemm_f32x2<H_, 0, 1><<<dim3(32, B_ / 64), 128>>>(
            3, nullptr, H_, w3, N_, b3 + (size_t)l * N_, logdet, updated);
    }

    merge_kernel<<<B_, 256>>>(x);
}